// round 13
// baseline (speedup 1.0000x reference)
#include <cuda_runtime.h>
#include <cuda_bf16.h>
#include <cstdint>
#include <cstddef>

#define BATCH 32
#define SEQ 2048
#define DA 32
#define HID 128
#define DS 64
#define NTOK (BATCH * SEQ)       /* 65536 */
#define TRANS_N (DS * DS)        /* 4096  */

/* Scratch: __device__ globals (no allocation allowed). */
__device__ __nv_bfloat16 g_h1h[(size_t)NTOK * HID];     /* 16 MB */
__device__ __nv_bfloat16 g_h1l[(size_t)NTOK * HID];     /* 16 MB */
__device__ __nv_bfloat16 g_w2hT[(size_t)TRANS_N * HID]; /* 1 MB, [n][k] */
__device__ __nv_bfloat16 g_w2lT[(size_t)TRANS_N * HID]; /* 1 MB */
__device__ float g_trans[(size_t)NTOK * TRANS_N];       /* 1 GiB */

/* ------------------------------------------------------------------ */
/* Kernel A: h1 = relu(relu(a@w0+b0)@w1 + b1); emit bf16 hi/lo split.  */
/* ------------------------------------------------------------------ */
__global__ __launch_bounds__(256) void mlp01_kernel(
    const float* __restrict__ actions, const float* __restrict__ w0,
    const float* __restrict__ b0, const float* __restrict__ w1,
    const float* __restrict__ b1)
{
    __shared__ float a_s[64 * DA];
    __shared__ float h0T[HID * 68];

    const int tid = threadIdx.x;
    const int tok0 = blockIdx.x * 64;

#pragma unroll
    for (int p = 0; p < 2; p++) {
        int u = p * 256 + tid;
        int tok = u >> 3;
        int c = (u & 7) * 4;
        float4 v = *reinterpret_cast<const float4*>(
            &actions[(size_t)(tok0 + tok) * DA + c]);
        a_s[tok * DA + c + 0] = v.x;
        a_s[tok * DA + c + 1] = v.y;
        a_s[tok * DA + c + 2] = v.z;
        a_s[tok * DA + c + 3] = v.w;
    }
    __syncthreads();

    const int j  = tid & 127;
    const int hi = tid >> 7;

    float w0c[DA];
#pragma unroll
    for (int k = 0; k < DA; k++) w0c[k] = w0[k * HID + j];
    const float b0v = b0[j];

    for (int o = 0; o < 32; o++) {
        int tok = o * 2 + hi;
        float acc = b0v;
#pragma unroll
        for (int k = 0; k < DA; k++) acc += a_s[tok * DA + k] * w0c[k];
        h0T[j * 68 + tok] = fmaxf(acc, 0.f);
    }
    __syncthreads();

    float accs[32];
#pragma unroll
    for (int m = 0; m < 32; m++) accs[m] = 0.f;
    const int m0 = hi * 32;

#pragma unroll 2
    for (int k = 0; k < HID; k++) {
        float wv = w1[k * HID + j];
        const float4* hp = reinterpret_cast<const float4*>(&h0T[k * 68 + m0]);
#pragma unroll
        for (int m4 = 0; m4 < 8; m4++) {
            float4 hv = hp[m4];
            accs[m4 * 4 + 0] += hv.x * wv;
            accs[m4 * 4 + 1] += hv.y * wv;
            accs[m4 * 4 + 2] += hv.z * wv;
            accs[m4 * 4 + 3] += hv.w * wv;
        }
    }
    const float b1v = b1[j];
#pragma unroll
    for (int m = 0; m < 32; m++) {
        float h = fmaxf(accs[m] + b1v, 0.f);
        __nv_bfloat16 h_hi = __float2bfloat16(h);
        __nv_bfloat16 h_lo = __float2bfloat16(h - __bfloat162float(h_hi));
        size_t idx = (size_t)(tok0 + m0 + m) * HID + j;
        g_h1h[idx] = h_hi;
        g_h1l[idx] = h_lo;
    }
}

/* ------------------------------------------------------------------ */
/* Kernel A2: transpose+split w2 [128,4096] -> w2hT/w2lT [4096,128].   */
/* ------------------------------------------------------------------ */
__global__ __launch_bounds__(256) void convw2_kernel(const float* __restrict__ w2)
{
    __shared__ float tile[32][33];
    const int n0 = blockIdx.x * 32;
    const int k0 = blockIdx.y * 32;
    const int tx = threadIdx.x;          /* 0..31 */
    const int ty = threadIdx.y;          /* 0..7  */

#pragma unroll
    for (int p = 0; p < 4; p++)
        tile[ty + p * 8][tx] = w2[(size_t)(k0 + ty + p * 8) * TRANS_N + n0 + tx];
    __syncthreads();

#pragma unroll
    for (int p = 0; p < 4; p++) {
        float v = tile[tx][ty + p * 8];
        __nv_bfloat16 vh = __float2bfloat16(v);
        __nv_bfloat16 vl = __float2bfloat16(v - __bfloat162float(vh));
        size_t o = (size_t)(n0 + ty + p * 8) * HID + k0 + tx;
        g_w2hT[o] = vh;
        g_w2lT[o] = vl;
    }
}

/* ------------------------------------------------------------------ */
/* Kernel B: split-bf16 GEMM via mma.sync (HMMA). Unchanged from R6.   */
/* ------------------------------------------------------------------ */
#define CHUNK_BYTES 16384u
#define STAGE_BYTES (2u * CHUNK_BYTES)
#define GB_DSMEM (2u * STAGE_BYTES)  /* 64 KB */

static __device__ __forceinline__ void ldmx4(uint32_t& r0, uint32_t& r1,
                                             uint32_t& r2, uint32_t& r3,
                                             uint32_t addr)
{
    asm volatile("ldmatrix.sync.aligned.m8n8.x4.shared.b16 {%0,%1,%2,%3}, [%4];"
                 : "=r"(r0), "=r"(r1), "=r"(r2), "=r"(r3) : "r"(addr));
}

static __device__ __forceinline__ void mma16816(float* c, const uint32_t* a,
                                                const uint32_t* b)
{
    asm volatile(
        "mma.sync.aligned.m16n8k16.row.col.f32.bf16.bf16.f32 "
        "{%0,%1,%2,%3}, {%4,%5,%6,%7}, {%8,%9}, {%0,%1,%2,%3};"
        : "+f"(c[0]), "+f"(c[1]), "+f"(c[2]), "+f"(c[3])
        : "r"(a[0]), "r"(a[1]), "r"(a[2]), "r"(a[3]), "r"(b[0]), "r"(b[1]));
}

__global__ __launch_bounds__(256, 2) void gemm_mma_kernel(
    const float* __restrict__ b2)
{
    extern __shared__ __align__(128) char sm[];

    const int tid = threadIdx.x;
    const int wid = tid >> 5;
    const int lane = tid & 31;
    const size_t m0 = (size_t)blockIdx.y * 128;
    const int n0 = blockIdx.x * 128;

    const int m_w = (wid & 1) * 64;
    const int n_w = (wid >> 1) * 32;

    const uint32_t smb = (uint32_t)__cvta_generic_to_shared(sm);

    auto load_chunk = [&](int c) {
        const __nv_bfloat16* ap = (c < 4) ? g_h1h : g_h1l;
        const __nv_bfloat16* bp = (c == 2 || c == 3) ? g_w2lT : g_w2hT;
        const int koff = (c & 1) * 64;
        const uint32_t Ab = smb + (uint32_t)(c & 1) * STAGE_BYTES;
        const uint32_t Bb = Ab + CHUNK_BYTES;
#pragma unroll
        for (int q = 0; q < 4; q++) {
            int u = q * 256 + tid;
            int row = u >> 3;
            int col8 = u & 7;
            uint32_t dst = (uint32_t)((row * 8 + (col8 ^ (row & 7))) * 16);
            const char* srcA = (const char*)(ap + (m0 + row) * HID + koff) + col8 * 16;
            const char* srcB = (const char*)(bp + (size_t)(n0 + row) * HID + koff) + col8 * 16;
            asm volatile("cp.async.cg.shared.global [%0], [%1], 16;"
                         :: "r"(Ab + dst), "l"(srcA));
            asm volatile("cp.async.cg.shared.global [%0], [%1], 16;"
                         :: "r"(Bb + dst), "l"(srcB));
        }
        asm volatile("cp.async.commit_group;" ::: "memory");
    };

    float acc[4][4][4];
#pragma unroll
    for (int i = 0; i < 4; i++)
#pragma unroll
        for (int j = 0; j < 4; j++)
#pragma unroll
            for (int q = 0; q < 4; q++) acc[i][j][q] = 0.f;

    const int a_row = lane & 15;
    const int a_ksel = lane >> 4;
    const int b_row = (lane & 7) | ((lane & 16) >> 1);
    const int b_ksel = (lane >> 3) & 1;

    load_chunk(0);

    for (int c = 0; c < 6; c++) {
        if (c < 5) load_chunk(c + 1);
        if (c < 5) asm volatile("cp.async.wait_group 1;" ::: "memory");
        else       asm volatile("cp.async.wait_group 0;" ::: "memory");
        __syncthreads();

        const uint32_t Ab = smb + (uint32_t)(c & 1) * STAGE_BYTES;
        const uint32_t Bb = Ab + CHUNK_BYTES;

#pragma unroll
        for (int k16 = 0; k16 < 4; k16++) {
            uint32_t afr[4][4];
            uint32_t bfr[4][2];
#pragma unroll
            for (int mi = 0; mi < 4; mi++) {
                int row = m_w + mi * 16 + a_row;
                int ku = (k16 * 2 + a_ksel) ^ (row & 7);
                ldmx4(afr[mi][0], afr[mi][1], afr[mi][2], afr[mi][3],
                      Ab + (uint32_t)((row * 8 + ku) * 16));
            }
#pragma unroll
            for (int np = 0; np < 2; np++) {
                int row = n_w + np * 16 + b_row;
                int ku = (k16 * 2 + b_ksel) ^ (row & 7);
                uint32_t r0, r1, r2, r3;
                ldmx4(r0, r1, r2, r3, Bb + (uint32_t)((row * 8 + ku) * 16));
                bfr[np * 2 + 0][0] = r0; bfr[np * 2 + 0][1] = r1;
                bfr[np * 2 + 1][0] = r2; bfr[np * 2 + 1][1] = r3;
            }
#pragma unroll
            for (int mi = 0; mi < 4; mi++)
#pragma unroll
                for (int ni = 0; ni < 4; ni++)
                    mma16816(acc[mi][ni], afr[mi], bfr[ni]);
        }
        __syncthreads();
    }

    float2 bias[4];
#pragma unroll
    for (int ni = 0; ni < 4; ni++) {
        int col = n0 + n_w + ni * 8 + (lane & 3) * 2;
        bias[ni] = *reinterpret_cast<const float2*>(&b2[col]);
    }
#pragma unroll
    for (int mi = 0; mi < 4; mi++) {
        size_t r0 = m0 + m_w + mi * 16 + (lane >> 2);
#pragma unroll
        for (int ni = 0; ni < 4; ni++) {
            int col = n0 + n_w + ni * 8 + (lane & 3) * 2;
            float2 v0 = make_float2(acc[mi][ni][0] + bias[ni].x,
                                    acc[mi][ni][1] + bias[ni].y);
            float2 v1 = make_float2(acc[mi][ni][2] + bias[ni].x,
                                    acc[mi][ni][3] + bias[ni].y);
            *reinterpret_cast<float2*>(&g_trans[r0 * TRANS_N + col]) = v0;
            *reinterpret_cast<float2*>(&g_trans[(r0 + 8) * TRANS_N + col]) = v1;
        }
    }
}

/* ------------------------------------------------------------------ */
/* Kernel C: bulk-sync scan, T loaded global->register (NO smem for T).*/
/*  - 192 threads. Warps 0-3 compute: thread (jg=tid&15, ib=tid>>4)    */
/*    owns cols jg*4..+3, rows ib*8..+7. 8x LDG.128/step, coalesced    */
/*    (4 full 128B lines per instr), double-buffered, distance 2.      */
/*  - Warps 4-5: parity-split l2norm + output (proven R11/R12).        */
/*  - Phase B (threads 0-63): 8-way partial combine + relu + g=1/4     */
/*    lag-4 exact-p2 rescale (proven stable since R10).                */
/* Removes the 256-wavefront/step crossbar floor of the smem design.   */
/* ------------------------------------------------------------------ */
#define SC_RING 16

__global__ __launch_bounds__(192, 1) void scan_kernel(
    const float* __restrict__ init_hidden, float* __restrict__ out)
{
    __shared__ __align__(16) float u_ring[SC_RING][DS];
    __shared__ float inv_ring[SC_RING];
    __shared__ __align__(16) float p_s[8][DS];   /* [ib][j] partials */
    __shared__ float wsum[2];

    const int tid = threadIdx.x;
    const int b = blockIdx.x;
    const int lane = tid & 31;
    const int wid = tid >> 5;
    const float* __restrict__ trans = g_trans + (size_t)b * SEQ * TRANS_N;

    /* ---- init: normalized initial hidden into u_ring[15] ---- */
    float v0 = 0.f;
    if (tid < 64) {
        v0 = init_hidden[tid];
        float s = v0 * v0;
        s += __shfl_xor_sync(0xffffffffu, s, 16);
        s += __shfl_xor_sync(0xffffffffu, s, 8);
        s += __shfl_xor_sync(0xffffffffu, s, 4);
        s += __shfl_xor_sync(0xffffffffu, s, 2);
        s += __shfl_xor_sync(0xffffffffu, s, 1);
        if (lane == 0) wsum[tid >> 5] = s;
    }
    __syncthreads();
    if (tid < 64) {
        float inv = 1.f / fmaxf(sqrtf(wsum[0] + wsum[1]), 1e-12f);
        u_ring[SC_RING - 1][tid] = v0 * inv;
    }
    __syncthreads();

    const int jg = tid & 15;          /* column group (4 cols)   */
    const int ib = tid >> 4;          /* row block (8 rows)      */

    /* T element base for this thread: row ib*8, col jg*4 */
    const float* __restrict__ Tbase = trans + (size_t)(ib * 8) * 64 + jg * 4;

    float4 Tr[2][8];
    if (wid < 4) {
        /* prologue: prefetch steps 0 and 1 */
#pragma unroll
        for (int d = 0; d < 2; d++) {
            const float* src = Tbase + (size_t)d * TRANS_N;
#pragma unroll
            for (int k = 0; k < 8; k++)
                Tr[d][k] = *reinterpret_cast<const float4*>(src + k * 64);
        }
    }

    for (int t = 0; t <= SEQ; t++) {
        /* ---------------- phase A ---------------- */
        if (wid < 4) {
            if (t < SEQ) {
                const float4* up = reinterpret_cast<const float4*>(
                    &u_ring[(t + SC_RING - 1) & (SC_RING - 1)][ib * 8]);
                float4 ua = up[0];
                float4 ub = up[1];
                const float4* Tc = Tr[t & 1];
                float4 acc;
                acc.x = ua.x * Tc[0].x; acc.y = ua.x * Tc[0].y;
                acc.z = ua.x * Tc[0].z; acc.w = ua.x * Tc[0].w;
                acc.x = fmaf(ua.y, Tc[1].x, acc.x);
                acc.y = fmaf(ua.y, Tc[1].y, acc.y);
                acc.z = fmaf(ua.y, Tc[1].z, acc.z);
                acc.w = fmaf(ua.y, Tc[1].w, acc.w);
                acc.x = fmaf(ua.z, Tc[2].x, acc.x);
                acc.y = fmaf(ua.z, Tc[2].y, acc.y);
                acc.z = fmaf(ua.z, Tc[2].z, acc.z);
                acc.w = fmaf(ua.z, Tc[2].w, acc.w);
                acc.x = fmaf(ua.w, Tc[3].x, acc.x);
                acc.y = fmaf(ua.w, Tc[3].y, acc.y);
                acc.z = fmaf(ua.w, Tc[3].z, acc.z);
                acc.w = fmaf(ua.w, Tc[3].w, acc.w);
                acc.x = fmaf(ub.x, Tc[4].x, acc.x);
                acc.y = fmaf(ub.x, Tc[4].y, acc.y);
                acc.z = fmaf(ub.x, Tc[4].z, acc.z);
                acc.w = fmaf(ub.x, Tc[4].w, acc.w);
                acc.x = fmaf(ub.y, Tc[5].x, acc.x);
                acc.y = fmaf(ub.y, Tc[5].y, acc.y);
                acc.z = fmaf(ub.y, Tc[5].z, acc.z);
                acc.w = fmaf(ub.y, Tc[5].w, acc.w);
                acc.x = fmaf(ub.z, Tc[6].x, acc.x);
                acc.y = fmaf(ub.z, Tc[6].y, acc.y);
                acc.z = fmaf(ub.z, Tc[6].z, acc.z);
                acc.w = fmaf(ub.z, Tc[6].w, acc.w);
                acc.x = fmaf(ub.w, Tc[7].x, acc.x);
                acc.y = fmaf(ub.w, Tc[7].y, acc.y);
                acc.z = fmaf(ub.w, Tc[7].z, acc.z);
                acc.w = fmaf(ub.w, Tc[7].w, acc.w);
                *reinterpret_cast<float4*>(&p_s[ib][jg * 4]) = acc;

                /* prefetch step t+2 into the buffer just consumed */
                if (t + 2 < SEQ) {
                    const float* src = Tbase + (size_t)(t + 2) * TRANS_N;
#pragma unroll
                    for (int k = 0; k < 8; k++)
                        Tr[t & 1][k] =
                            *reinterpret_cast<const float4*>(src + k * 64);
                }
            }
        } else {
            /* norm warps 4-5, parity split */
            const int tp = t - 1;
            if (tp >= 0 && (tp & 1) == (wid - 4)) {
                float2 u2 = *reinterpret_cast<const float2*>(
                    &u_ring[tp & (SC_RING - 1)][lane * 2]);
                float ss = fmaf(u2.x, u2.x, u2.y * u2.y);
                ss += __shfl_xor_sync(0xffffffffu, ss, 16);
                ss += __shfl_xor_sync(0xffffffffu, ss, 8);
                ss += __shfl_xor_sync(0xffffffffu, ss, 4);
                ss += __shfl_xor_sync(0xffffffffu, ss, 2);
                ss += __shfl_xor_sync(0xffffffffu, ss, 1);
                float inv = 1.f / fmaxf(sqrtf(ss), 1e-12f);
                *reinterpret_cast<float2*>(
                    &out[((size_t)b * SEQ + tp) * DS + lane * 2]) =
                    make_float2(u2.x * inv, u2.y * inv);
                if (lane == 0) inv_ring[tp & (SC_RING - 1)] = inv;
            }
        }
        __syncthreads();

        /* ---------------- phase B ---------------- */
        if (t < SEQ && tid < 64) {
            float z = ((p_s[0][tid] + p_s[1][tid]) +
                       (p_s[2][tid] + p_s[3][tid])) +
                      ((p_s[4][tid] + p_s[5][tid]) +
                       (p_s[6][tid] + p_s[7][tid]));
            float u = fmaxf(z, 0.f);
            if (t >= 4) {
                /* g = 1/4 damped exact-p2 rescale (proven stable) */
                unsigned ib2 = __float_as_uint(
                    inv_ring[(t - 4) & (SC_RING - 1)]);
                int e = (int)((ib2 >> 23) & 0xFFu) - 127;
                e = max(-96, min(96, e));
                float s = __uint_as_float((unsigned)(127 + (e >> 2)) << 23);
                u *= s;
            }
            u_ring[t & (SC_RING - 1)][tid] = u;
        }
        __syncthreads();
    }
}

/* ------------------------------------------------------------------ */
extern "C" void kernel_launch(void* const* d_in, const int* in_sizes, int n_in,
                              void* d_out, int out_size)
{
    const float* actions = (const float*)d_in[0];
    const float* w0 = (const float*)d_in[1];
    const float* b0 = (const float*)d_in[2];
    const float* w1 = (const float*)d_in[3];
    const float* b1 = (const float*)d_in[4];
    const float* w2 = (const float*)d_in[5];
    const float* b2 = (const float*)d_in[6];
    const float* ih = (const float*)d_in[7];
    float* out = (float*)d_out;

    mlp01_kernel<<<NTOK / 64, 256>>>(actions, w0, b0, w1, b1);
    convw2_kernel<<<dim3(TRANS_N / 32, HID / 32), dim3(32, 8)>>>(w2);

    cudaFuncSetAttribute(gemm_mma_kernel,
                         cudaFuncAttributeMaxDynamicSharedMemorySize, GB_DSMEM);
    gemm_mma_kernel<<<dim3(TRANS_N / 128, NTOK / 128), 256, GB_DSMEM>>>(b2);

    scan_kernel<<<BATCH, 192>>>(ih, out);
}

// round 15
// speedup vs baseline: 1.4665x; 1.4665x over previous
#include <cuda_runtime.h>
#include <cuda_bf16.h>
#include <cstdint>
#include <cstddef>

#define BATCH 32
#define SEQ 2048
#define DA 32
#define HID 128
#define DS 64
#define NTOK (BATCH * SEQ)       /* 65536 */
#define TRANS_N (DS * DS)        /* 4096  */

/* Scratch: __device__ globals (no allocation allowed). */
__device__ __nv_bfloat16 g_h1h[(size_t)NTOK * HID];     /* 16 MB */
__device__ __nv_bfloat16 g_h1l[(size_t)NTOK * HID];     /* 16 MB */
__device__ __nv_bfloat16 g_w2hT[(size_t)TRANS_N * HID]; /* 1 MB, [n][k] */
__device__ __nv_bfloat16 g_w2lT[(size_t)TRANS_N * HID]; /* 1 MB */
__device__ float g_trans[(size_t)NTOK * TRANS_N];       /* 1 GiB */

/* ------------------------------------------------------------------ */
/* Kernel A: h1 = relu(relu(a@w0+b0)@w1 + b1); emit bf16 hi/lo split.  */
/* ------------------------------------------------------------------ */
__global__ __launch_bounds__(256) void mlp01_kernel(
    const float* __restrict__ actions, const float* __restrict__ w0,
    const float* __restrict__ b0, const float* __restrict__ w1,
    const float* __restrict__ b1)
{
    __shared__ float a_s[64 * DA];
    __shared__ float h0T[HID * 68];

    const int tid = threadIdx.x;
    const int tok0 = blockIdx.x * 64;

#pragma unroll
    for (int p = 0; p < 2; p++) {
        int u = p * 256 + tid;
        int tok = u >> 3;
        int c = (u & 7) * 4;
        float4 v = *reinterpret_cast<const float4*>(
            &actions[(size_t)(tok0 + tok) * DA + c]);
        a_s[tok * DA + c + 0] = v.x;
        a_s[tok * DA + c + 1] = v.y;
        a_s[tok * DA + c + 2] = v.z;
        a_s[tok * DA + c + 3] = v.w;
    }
    __syncthreads();

    const int j  = tid & 127;
    const int hi = tid >> 7;

    float w0c[DA];
#pragma unroll
    for (int k = 0; k < DA; k++) w0c[k] = w0[k * HID + j];
    const float b0v = b0[j];

    for (int o = 0; o < 32; o++) {
        int tok = o * 2 + hi;
        float acc = b0v;
#pragma unroll
        for (int k = 0; k < DA; k++) acc += a_s[tok * DA + k] * w0c[k];
        h0T[j * 68 + tok] = fmaxf(acc, 0.f);
    }
    __syncthreads();

    float accs[32];
#pragma unroll
    for (int m = 0; m < 32; m++) accs[m] = 0.f;
    const int m0 = hi * 32;

#pragma unroll 2
    for (int k = 0; k < HID; k++) {
        float wv = w1[k * HID + j];
        const float4* hp = reinterpret_cast<const float4*>(&h0T[k * 68 + m0]);
#pragma unroll
        for (int m4 = 0; m4 < 8; m4++) {
            float4 hv = hp[m4];
            accs[m4 * 4 + 0] += hv.x * wv;
            accs[m4 * 4 + 1] += hv.y * wv;
            accs[m4 * 4 + 2] += hv.z * wv;
            accs[m4 * 4 + 3] += hv.w * wv;
        }
    }
    const float b1v = b1[j];
#pragma unroll
    for (int m = 0; m < 32; m++) {
        float h = fmaxf(accs[m] + b1v, 0.f);
        __nv_bfloat16 h_hi = __float2bfloat16(h);
        __nv_bfloat16 h_lo = __float2bfloat16(h - __bfloat162float(h_hi));
        size_t idx = (size_t)(tok0 + m0 + m) * HID + j;
        g_h1h[idx] = h_hi;
        g_h1l[idx] = h_lo;
    }
}

/* ------------------------------------------------------------------ */
/* Kernel A2: transpose+split w2 [128,4096] -> w2hT/w2lT [4096,128].   */
/* ------------------------------------------------------------------ */
__global__ __launch_bounds__(256) void convw2_kernel(const float* __restrict__ w2)
{
    __shared__ float tile[32][33];
    const int n0 = blockIdx.x * 32;
    const int k0 = blockIdx.y * 32;
    const int tx = threadIdx.x;          /* 0..31 */
    const int ty = threadIdx.y;          /* 0..7  */

#pragma unroll
    for (int p = 0; p < 4; p++)
        tile[ty + p * 8][tx] = w2[(size_t)(k0 + ty + p * 8) * TRANS_N + n0 + tx];
    __syncthreads();

#pragma unroll
    for (int p = 0; p < 4; p++) {
        float v = tile[tx][ty + p * 8];
        __nv_bfloat16 vh = __float2bfloat16(v);
        __nv_bfloat16 vl = __float2bfloat16(v - __bfloat162float(vh));
        size_t o = (size_t)(n0 + ty + p * 8) * HID + k0 + tx;
        g_w2hT[o] = vh;
        g_w2lT[o] = vl;
    }
}

/* ------------------------------------------------------------------ */
/* Kernel B: split-bf16 GEMM via mma.sync (HMMA). Unchanged from R6.   */
/* ------------------------------------------------------------------ */
#define CHUNK_BYTES 16384u
#define STAGE_BYTES (2u * CHUNK_BYTES)
#define GB_DSMEM (2u * STAGE_BYTES)  /* 64 KB */

static __device__ __forceinline__ void ldmx4(uint32_t& r0, uint32_t& r1,
                                             uint32_t& r2, uint32_t& r3,
                                             uint32_t addr)
{
    asm volatile("ldmatrix.sync.aligned.m8n8.x4.shared.b16 {%0,%1,%2,%3}, [%4];"
                 : "=r"(r0), "=r"(r1), "=r"(r2), "=r"(r3) : "r"(addr));
}

static __device__ __forceinline__ void mma16816(float* c, const uint32_t* a,
                                                const uint32_t* b)
{
    asm volatile(
        "mma.sync.aligned.m16n8k16.row.col.f32.bf16.bf16.f32 "
        "{%0,%1,%2,%3}, {%4,%5,%6,%7}, {%8,%9}, {%0,%1,%2,%3};"
        : "+f"(c[0]), "+f"(c[1]), "+f"(c[2]), "+f"(c[3])
        : "r"(a[0]), "r"(a[1]), "r"(a[2]), "r"(a[3]), "r"(b[0]), "r"(b[1]));
}

__global__ __launch_bounds__(256, 2) void gemm_mma_kernel(
    const float* __restrict__ b2)
{
    extern __shared__ __align__(128) char sm[];

    const int tid = threadIdx.x;
    const int wid = tid >> 5;
    const int lane = tid & 31;
    const size_t m0 = (size_t)blockIdx.y * 128;
    const int n0 = blockIdx.x * 128;

    const int m_w = (wid & 1) * 64;
    const int n_w = (wid >> 1) * 32;

    const uint32_t smb = (uint32_t)__cvta_generic_to_shared(sm);

    auto load_chunk = [&](int c) {
        const __nv_bfloat16* ap = (c < 4) ? g_h1h : g_h1l;
        const __nv_bfloat16* bp = (c == 2 || c == 3) ? g_w2lT : g_w2hT;
        const int koff = (c & 1) * 64;
        const uint32_t Ab = smb + (uint32_t)(c & 1) * STAGE_BYTES;
        const uint32_t Bb = Ab + CHUNK_BYTES;
#pragma unroll
        for (int q = 0; q < 4; q++) {
            int u = q * 256 + tid;
            int row = u >> 3;
            int col8 = u & 7;
            uint32_t dst = (uint32_t)((row * 8 + (col8 ^ (row & 7))) * 16);
            const char* srcA = (const char*)(ap + (m0 + row) * HID + koff) + col8 * 16;
            const char* srcB = (const char*)(bp + (size_t)(n0 + row) * HID + koff) + col8 * 16;
            asm volatile("cp.async.cg.shared.global [%0], [%1], 16;"
                         :: "r"(Ab + dst), "l"(srcA));
            asm volatile("cp.async.cg.shared.global [%0], [%1], 16;"
                         :: "r"(Bb + dst), "l"(srcB));
        }
        asm volatile("cp.async.commit_group;" ::: "memory");
    };

    float acc[4][4][4];
#pragma unroll
    for (int i = 0; i < 4; i++)
#pragma unroll
        for (int j = 0; j < 4; j++)
#pragma unroll
            for (int q = 0; q < 4; q++) acc[i][j][q] = 0.f;

    const int a_row = lane & 15;
    const int a_ksel = lane >> 4;
    const int b_row = (lane & 7) | ((lane & 16) >> 1);
    const int b_ksel = (lane >> 3) & 1;

    load_chunk(0);

    for (int c = 0; c < 6; c++) {
        if (c < 5) load_chunk(c + 1);
        if (c < 5) asm volatile("cp.async.wait_group 1;" ::: "memory");
        else       asm volatile("cp.async.wait_group 0;" ::: "memory");
        __syncthreads();

        const uint32_t Ab = smb + (uint32_t)(c & 1) * STAGE_BYTES;
        const uint32_t Bb = Ab + CHUNK_BYTES;

#pragma unroll
        for (int k16 = 0; k16 < 4; k16++) {
            uint32_t afr[4][4];
            uint32_t bfr[4][2];
#pragma unroll
            for (int mi = 0; mi < 4; mi++) {
                int row = m_w + mi * 16 + a_row;
                int ku = (k16 * 2 + a_ksel) ^ (row & 7);
                ldmx4(afr[mi][0], afr[mi][1], afr[mi][2], afr[mi][3],
                      Ab + (uint32_t)((row * 8 + ku) * 16));
            }
#pragma unroll
            for (int np = 0; np < 2; np++) {
                int row = n_w + np * 16 + b_row;
                int ku = (k16 * 2 + b_ksel) ^ (row & 7);
                uint32_t r0, r1, r2, r3;
                ldmx4(r0, r1, r2, r3, Bb + (uint32_t)((row * 8 + ku) * 16));
                bfr[np * 2 + 0][0] = r0; bfr[np * 2 + 0][1] = r1;
                bfr[np * 2 + 1][0] = r2; bfr[np * 2 + 1][1] = r3;
            }
#pragma unroll
            for (int mi = 0; mi < 4; mi++)
#pragma unroll
                for (int ni = 0; ni < 4; ni++)
                    mma16816(acc[mi][ni], afr[mi], bfr[ni]);
        }
        __syncthreads();
    }

    float2 bias[4];
#pragma unroll
    for (int ni = 0; ni < 4; ni++) {
        int col = n0 + n_w + ni * 8 + (lane & 3) * 2;
        bias[ni] = *reinterpret_cast<const float2*>(&b2[col]);
    }
#pragma unroll
    for (int mi = 0; mi < 4; mi++) {
        size_t r0 = m0 + m_w + mi * 16 + (lane >> 2);
#pragma unroll
        for (int ni = 0; ni < 4; ni++) {
            int col = n0 + n_w + ni * 8 + (lane & 3) * 2;
            float2 v0 = make_float2(acc[mi][ni][0] + bias[ni].x,
                                    acc[mi][ni][1] + bias[ni].y);
            float2 v1 = make_float2(acc[mi][ni][2] + bias[ni].x,
                                    acc[mi][ni][3] + bias[ni].y);
            *reinterpret_cast<float2*>(&g_trans[r0 * TRANS_N + col]) = v0;
            *reinterpret_cast<float2*>(&g_trans[(r0 + 8) * TRANS_N + col]) = v1;
        }
    }
}

/* ------------------------------------------------------------------ */
/* Kernel C: bulk-sync scan, T global->register, loop UNROLLED x2 so   */
/* the double buffer (Tr0/Tr1) is statically indexed — R13's dynamic   */
/* Tr[t&1] forced a local-memory spill (8 LDL+8 STL per step on the    */
/* critical path), which is what regressed it to 1.95 ms.              */
/*  - 192 threads; warps 0-3 compute (thread = 4 cols x 8 rows,        */
/*    8x coalesced LDG.128/step, prefetch distance 2, static regs);    */
/*  - warps 4-5 parity-split norm+store; phase B = combine + relu +    */
/*    proven g=1/4 lag-4 exact-p2 rescale.                             */
/* ------------------------------------------------------------------ */
#define SC_RING 16

__global__ __launch_bounds__(192, 1) void scan_kernel(
    const float* __restrict__ init_hidden, float* __restrict__ out)
{
    __shared__ __align__(16) float u_ring[SC_RING][DS];
    __shared__ float inv_ring[SC_RING];
    __shared__ __align__(16) float p_s[8][DS];   /* [ib][j] partials */
    __shared__ float wsum[2];

    const int tid = threadIdx.x;
    const int b = blockIdx.x;
    const int lane = tid & 31;
    const int wid = tid >> 5;
    const float* __restrict__ trans = g_trans + (size_t)b * SEQ * TRANS_N;

    /* ---- init: normalized initial hidden into u_ring[15] ---- */
    float v0 = 0.f;
    if (tid < 64) {
        v0 = init_hidden[tid];
        float s = v0 * v0;
        s += __shfl_xor_sync(0xffffffffu, s, 16);
        s += __shfl_xor_sync(0xffffffffu, s, 8);
        s += __shfl_xor_sync(0xffffffffu, s, 4);
        s += __shfl_xor_sync(0xffffffffu, s, 2);
        s += __shfl_xor_sync(0xffffffffu, s, 1);
        if (lane == 0) wsum[tid >> 5] = s;
    }
    __syncthreads();
    if (tid < 64) {
        float inv = 1.f / fmaxf(sqrtf(wsum[0] + wsum[1]), 1e-12f);
        u_ring[SC_RING - 1][tid] = v0 * inv;
    }
    __syncthreads();

    const int jg = tid & 15;          /* column group (4 cols) */
    const int ib = tid >> 4;          /* row block (8 rows)    */
    const float* __restrict__ Tbase = trans + (size_t)(ib * 8) * 64 + jg * 4;

    float4 Tr0[8], Tr1[8];            /* statically indexed — stays in regs */
    if (wid < 4) {
#pragma unroll
        for (int k = 0; k < 8; k++)
            Tr0[k] = *reinterpret_cast<const float4*>(Tbase + k * 64);
#pragma unroll
        for (int k = 0; k < 8; k++)
            Tr1[k] = *reinterpret_cast<const float4*>(
                Tbase + TRANS_N + k * 64);
    }

    /* matvec on a statically-named register buffer + prefetch t+2 */
#define SCAN_MATVEC(t, TBUF)                                               \
    do {                                                                   \
        const float4* up = reinterpret_cast<const float4*>(                \
            &u_ring[((t) + SC_RING - 1) & (SC_RING - 1)][ib * 8]);         \
        float4 ua = up[0];                                                 \
        float4 ub = up[1];                                                 \
        float4 acc;                                                        \
        acc.x = ua.x * TBUF[0].x; acc.y = ua.x * TBUF[0].y;                \
        acc.z = ua.x * TBUF[0].z; acc.w = ua.x * TBUF[0].w;                \
        acc.x = fmaf(ua.y, TBUF[1].x, acc.x);                              \
        acc.y = fmaf(ua.y, TBUF[1].y, acc.y);                              \
        acc.z = fmaf(ua.y, TBUF[1].z, acc.z);                              \
        acc.w = fmaf(ua.y, TBUF[1].w, acc.w);                              \
        acc.x = fmaf(ua.z, TBUF[2].x, acc.x);                              \
        acc.y = fmaf(ua.z, TBUF[2].y, acc.y);                              \
        acc.z = fmaf(ua.z, TBUF[2].z, acc.z);                              \
        acc.w = fmaf(ua.z, TBUF[2].w, acc.w);                              \
        acc.x = fmaf(ua.w, TBUF[3].x, acc.x);                              \
        acc.y = fmaf(ua.w, TBUF[3].y, acc.y);                              \
        acc.z = fmaf(ua.w, TBUF[3].z, acc.z);                              \
        acc.w = fmaf(ua.w, TBUF[3].w, acc.w);                              \
        acc.x = fmaf(ub.x, TBUF[4].x, acc.x);                              \
        acc.y = fmaf(ub.x, TBUF[4].y, acc.y);                              \
        acc.z = fmaf(ub.x, TBUF[4].z, acc.z);                              \
        acc.w = fmaf(ub.x, TBUF[4].w, acc.w);                              \
        acc.x = fmaf(ub.y, TBUF[5].x, acc.x);                              \
        acc.y = fmaf(ub.y, TBUF[5].y, acc.y);                              \
        acc.z = fmaf(ub.y, TBUF[5].z, acc.z);                              \
        acc.w = fmaf(ub.y, TBUF[5].w, acc.w);                              \
        acc.x = fmaf(ub.z, TBUF[6].x, acc.x);                              \
        acc.y = fmaf(ub.z, TBUF[6].y, acc.y);                              \
        acc.z = fmaf(ub.z, TBUF[6].z, acc.z);                              \
        acc.w = fmaf(ub.z, TBUF[6].w, acc.w);                              \
        acc.x = fmaf(ub.w, TBUF[7].x, acc.x);                              \
        acc.y = fmaf(ub.w, TBUF[7].y, acc.y);                              \
        acc.z = fmaf(ub.w, TBUF[7].z, acc.z);                              \
        acc.w = fmaf(ub.w, TBUF[7].w, acc.w);                              \
        *reinterpret_cast<float4*>(&p_s[ib][jg * 4]) = acc;                \
        if ((t) + 2 < SEQ) {                                               \
            const float* src = Tbase + (size_t)((t) + 2) * TRANS_N;        \
            _Pragma("unroll")                                              \
            for (int k = 0; k < 8; k++)                                    \
                TBUF[k] = *reinterpret_cast<const float4*>(src + k * 64);  \
        }                                                                  \
    } while (0)

#define SCAN_NORM(tp)                                                      \
    do {                                                                   \
        if ((tp) >= 0 && ((tp) & 1) == (wid - 4)) {                        \
            float2 u2 = *reinterpret_cast<const float2*>(                  \
                &u_ring[(tp) & (SC_RING - 1)][lane * 2]);                  \
            float ss = fmaf(u2.x, u2.x, u2.y * u2.y);                      \
            ss += __shfl_xor_sync(0xffffffffu, ss, 16);                    \
            ss += __shfl_xor_sync(0xffffffffu, ss, 8);                     \
            ss += __shfl_xor_sync(0xffffffffu, ss, 4);                     \
            ss += __shfl_xor_sync(0xffffffffu, ss, 2);                     \
            ss += __shfl_xor_sync(0xffffffffu, ss, 1);                     \
            float inv = 1.f / fmaxf(sqrtf(ss), 1e-12f);                    \
            *reinterpret_cast<float2*>(                                    \
                &out[((size_t)b * SEQ + (tp)) * DS + lane * 2]) =          \
                make_float2(u2.x * inv, u2.y * inv);                       \
            if (lane == 0) inv_ring[(tp) & (SC_RING - 1)] = inv;           \
        }                                                                  \
    } while (0)

#define SCAN_PHASEB(t)                                                     \
    do {                                                                   \
        if (tid < 64) {                                                    \
            float z = ((p_s[0][tid] + p_s[1][tid]) +                       \
                       (p_s[2][tid] + p_s[3][tid])) +                      \
                      ((p_s[4][tid] + p_s[5][tid]) +                       \
                       (p_s[6][tid] + p_s[7][tid]));                       \
            float u = fmaxf(z, 0.f);                                       \
            if ((t) >= 4) {                                                \
                unsigned ibq = __float_as_uint(                            \
                    inv_ring[((t) - 4) & (SC_RING - 1)]);                  \
                int e = (int)((ibq >> 23) & 0xFFu) - 127;                  \
                e = max(-96, min(96, e));                                  \
                float s = __uint_as_float(                                 \
                    (unsigned)(127 + (e >> 2)) << 23);                     \
                u *= s;                                                    \
            }                                                              \
            u_ring[(t) & (SC_RING - 1)][tid] = u;                          \
        }                                                                  \
    } while (0)

    for (int tt = 0; tt < SEQ; tt += 2) {
        /* ---- step tt (even): buffer Tr0 ---- */
        if (wid < 4) SCAN_MATVEC(tt, Tr0);
        else         SCAN_NORM(tt - 1);
        __syncthreads();
        SCAN_PHASEB(tt);
        __syncthreads();

        /* ---- step tt+1 (odd): buffer Tr1 ---- */
        if (wid < 4) SCAN_MATVEC(tt + 1, Tr1);
        else         SCAN_NORM(tt);
        __syncthreads();
        SCAN_PHASEB(tt + 1);
        __syncthreads();
    }
    /* epilogue: norm+store for the final step */
    if (wid >= 4) SCAN_NORM(SEQ - 1);

#undef SCAN_MATVEC
#undef SCAN_NORM
#undef SCAN_PHASEB
}

/* ------------------------------------------------------------------ */
extern "C" void kernel_launch(void* const* d_in, const int* in_sizes, int n_in,
                              void* d_out, int out_size)
{
    const float* actions = (const float*)d_in[0];
    const float* w0 = (const float*)d_in[1];
    const float* b0 = (const float*)d_in[2];
    const float* w1 = (const float*)d_in[3];
    const float* b1 = (const float*)d_in[4];
    const float* w2 = (const float*)d_in[5];
    const float* b2 = (const float*)d_in[6];
    const float* ih = (const float*)d_in[7];
    float* out = (float*)d_out;

    mlp01_kernel<<<NTOK / 64, 256>>>(actions, w0, b0, w1, b1);
    convw2_kernel<<<dim3(TRANS_N / 32, HID / 32), dim3(32, 8)>>>(w2);

    cudaFuncSetAttribute(gemm_mma_kernel,
                         cudaFuncAttributeMaxDynamicSharedMemorySize, GB_DSMEM);
    gemm_mma_kernel<<<dim3(TRANS_N / 128, NTOK / 128), 256, GB_DSMEM>>>(b2);

    scan_kernel<<<BATCH, 192>>>(ih, out);
}

// round 17
// speedup vs baseline: 1.4968x; 1.0206x over previous
#include <cuda_runtime.h>
#include <cuda_bf16.h>
#include <cstdint>
#include <cstddef>

#define BATCH 32
#define SEQ 2048
#define DA 32
#define HID 128
#define DS 64
#define NTOK (BATCH * SEQ)       /* 65536 */
#define TRANS_N (DS * DS)        /* 4096  */

/* Scratch: __device__ globals (no allocation allowed). */
__device__ __nv_bfloat16 g_h1h[(size_t)NTOK * HID];     /* 16 MB */
__device__ __nv_bfloat16 g_h1l[(size_t)NTOK * HID];     /* 16 MB */
__device__ __nv_bfloat16 g_w2hT[(size_t)TRANS_N * HID]; /* 1 MB, [n][k] */
__device__ __nv_bfloat16 g_w2lT[(size_t)TRANS_N * HID]; /* 1 MB */
__device__ float g_trans[(size_t)NTOK * TRANS_N];       /* 1 GiB */

/* ------------------------------------------------------------------ */
/* Kernel A: h1 = relu(relu(a@w0+b0)@w1 + b1); emit bf16 hi/lo split.  */
/* ------------------------------------------------------------------ */
__global__ __launch_bounds__(256) void mlp01_kernel(
    const float* __restrict__ actions, const float* __restrict__ w0,
    const float* __restrict__ b0, const float* __restrict__ w1,
    const float* __restrict__ b1)
{
    __shared__ float a_s[64 * DA];
    __shared__ float h0T[HID * 68];

    const int tid = threadIdx.x;
    const int tok0 = blockIdx.x * 64;

#pragma unroll
    for (int p = 0; p < 2; p++) {
        int u = p * 256 + tid;
        int tok = u >> 3;
        int c = (u & 7) * 4;
        float4 v = *reinterpret_cast<const float4*>(
            &actions[(size_t)(tok0 + tok) * DA + c]);
        a_s[tok * DA + c + 0] = v.x;
        a_s[tok * DA + c + 1] = v.y;
        a_s[tok * DA + c + 2] = v.z;
        a_s[tok * DA + c + 3] = v.w;
    }
    __syncthreads();

    const int j  = tid & 127;
    const int hi = tid >> 7;

    float w0c[DA];
#pragma unroll
    for (int k = 0; k < DA; k++) w0c[k] = w0[k * HID + j];
    const float b0v = b0[j];

    for (int o = 0; o < 32; o++) {
        int tok = o * 2 + hi;
        float acc = b0v;
#pragma unroll
        for (int k = 0; k < DA; k++) acc += a_s[tok * DA + k] * w0c[k];
        h0T[j * 68 + tok] = fmaxf(acc, 0.f);
    }
    __syncthreads();

    float accs[32];
#pragma unroll
    for (int m = 0; m < 32; m++) accs[m] = 0.f;
    const int m0 = hi * 32;

#pragma unroll 2
    for (int k = 0; k < HID; k++) {
        float wv = w1[k * HID + j];
        const float4* hp = reinterpret_cast<const float4*>(&h0T[k * 68 + m0]);
#pragma unroll
        for (int m4 = 0; m4 < 8; m4++) {
            float4 hv = hp[m4];
            accs[m4 * 4 + 0] += hv.x * wv;
            accs[m4 * 4 + 1] += hv.y * wv;
            accs[m4 * 4 + 2] += hv.z * wv;
            accs[m4 * 4 + 3] += hv.w * wv;
        }
    }
    const float b1v = b1[j];
#pragma unroll
    for (int m = 0; m < 32; m++) {
        float h = fmaxf(accs[m] + b1v, 0.f);
        __nv_bfloat16 h_hi = __float2bfloat16(h);
        __nv_bfloat16 h_lo = __float2bfloat16(h - __bfloat162float(h_hi));
        size_t idx = (size_t)(tok0 + m0 + m) * HID + j;
        g_h1h[idx] = h_hi;
        g_h1l[idx] = h_lo;
    }
}

/* ------------------------------------------------------------------ */
/* Kernel A2: transpose+split w2 [128,4096] -> w2hT/w2lT [4096,128].   */
/* ------------------------------------------------------------------ */
__global__ __launch_bounds__(256) void convw2_kernel(const float* __restrict__ w2)
{
    __shared__ float tile[32][33];
    const int n0 = blockIdx.x * 32;
    const int k0 = blockIdx.y * 32;
    const int tx = threadIdx.x;          /* 0..31 */
    const int ty = threadIdx.y;          /* 0..7  */

#pragma unroll
    for (int p = 0; p < 4; p++)
        tile[ty + p * 8][tx] = w2[(size_t)(k0 + ty + p * 8) * TRANS_N + n0 + tx];
    __syncthreads();

#pragma unroll
    for (int p = 0; p < 4; p++) {
        float v = tile[tx][ty + p * 8];
        __nv_bfloat16 vh = __float2bfloat16(v);
        __nv_bfloat16 vl = __float2bfloat16(v - __bfloat162float(vh));
        size_t o = (size_t)(n0 + ty + p * 8) * HID + k0 + tx;
        g_w2hT[o] = vh;
        g_w2lT[o] = vl;
    }
}

/* ------------------------------------------------------------------ */
/* Kernel B: split-bf16 GEMM (HMMA), B-resident, RACE-FIXED pipeline.  */
/* B chunks (Bh/Bl x k0/k64, 64 KB) resident; A streams 4 chunks thru  */
/* a 2-buffer ring. R16 BUG: load_a(c+2) was issued BEFORE chunk c     */
/* (same buffer) was consumed -> cp.async overwrote live data. Fix:    */
/* issue load_a(c+2) after the end-of-compute barrier of iter c.       */
/* ------------------------------------------------------------------ */
#define CHUNK_BYTES 16384u
#define GB_A_OFF (4u * CHUNK_BYTES)          /* A double buffer at 64 KB */
#define GB_DSMEM (6u * CHUNK_BYTES)          /* 96 KB */

static __device__ __forceinline__ void ldmx4(uint32_t& r0, uint32_t& r1,
                                             uint32_t& r2, uint32_t& r3,
                                             uint32_t addr)
{
    asm volatile("ldmatrix.sync.aligned.m8n8.x4.shared.b16 {%0,%1,%2,%3}, [%4];"
                 : "=r"(r0), "=r"(r1), "=r"(r2), "=r"(r3) : "r"(addr));
}

static __device__ __forceinline__ void mma16816(float* c, const uint32_t* a,
                                                const uint32_t* b)
{
    asm volatile(
        "mma.sync.aligned.m16n8k16.row.col.f32.bf16.bf16.f32 "
        "{%0,%1,%2,%3}, {%4,%5,%6,%7}, {%8,%9}, {%0,%1,%2,%3};"
        : "+f"(c[0]), "+f"(c[1]), "+f"(c[2]), "+f"(c[3])
        : "r"(a[0]), "r"(a[1]), "r"(a[2]), "r"(a[3]), "r"(b[0]), "r"(b[1]));
}

__global__ __launch_bounds__(256, 2) void gemm_mma_kernel(
    const float* __restrict__ b2)
{
    extern __shared__ __align__(128) char sm[];

    const int tid = threadIdx.x;
    const int wid = tid >> 5;
    const int lane = tid & 31;
    const size_t m0 = (size_t)blockIdx.y * 128;
    const int n0 = blockIdx.x * 128;

    const int m_w = (wid & 1) * 64;
    const int n_w = (wid >> 1) * 32;

    const uint32_t smb = (uint32_t)__cvta_generic_to_shared(sm);

    /* ---- B chunks resident: 0:Bh k0, 1:Bh k64, 2:Bl k0, 3:Bl k64 ---- */
    {
#pragma unroll
        for (int bc = 0; bc < 4; bc++) {
            const __nv_bfloat16* bp = (bc < 2) ? g_w2hT : g_w2lT;
            const int koff = (bc & 1) * 64;
            const uint32_t Bb = smb + (uint32_t)bc * CHUNK_BYTES;
#pragma unroll
            for (int q = 0; q < 4; q++) {
                int u = q * 256 + tid;
                int row = u >> 3;
                int col8 = u & 7;
                uint32_t dst = (uint32_t)((row * 8 + (col8 ^ (row & 7))) * 16);
                const char* src =
                    (const char*)(bp + (size_t)(n0 + row) * HID + koff) + col8 * 16;
                asm volatile("cp.async.cg.shared.global [%0], [%1], 16;"
                             :: "r"(Bb + dst), "l"(src));
            }
        }
        asm volatile("cp.async.commit_group;" ::: "memory");   /* group: B */
    }

    /* A chunk c: 0:Ah k0, 1:Ah k64, 2:Al k0, 3:Al k64 */
    auto load_a = [&](int c) {
        const __nv_bfloat16* ap = (c < 2) ? g_h1h : g_h1l;
        const int koff = (c & 1) * 64;
        const uint32_t Ab = smb + GB_A_OFF + (uint32_t)(c & 1) * CHUNK_BYTES;
#pragma unroll
        for (int q = 0; q < 4; q++) {
            int u = q * 256 + tid;
            int row = u >> 3;
            int col8 = u & 7;
            uint32_t dst = (uint32_t)((row * 8 + (col8 ^ (row & 7))) * 16);
            const char* src =
                (const char*)(ap + (m0 + row) * HID + koff) + col8 * 16;
            asm volatile("cp.async.cg.shared.global [%0], [%1], 16;"
                         :: "r"(Ab + dst), "l"(src));
        }
        asm volatile("cp.async.commit_group;" ::: "memory");
    };

    float acc[4][4][4];
#pragma unroll
    for (int i = 0; i < 4; i++)
#pragma unroll
        for (int j = 0; j < 4; j++)
#pragma unroll
            for (int q = 0; q < 4; q++) acc[i][j][q] = 0.f;

    const int a_row = lane & 15;
    const int a_ksel = lane >> 4;
    const int b_row = (lane & 7) | ((lane & 16) >> 1);
    const int b_ksel = (lane >> 3) & 1;

    load_a(0);
    load_a(1);

    for (int c = 0; c < 4; c++) {
        /* wait until chunk c (and, at c=0, the B group) is complete;
           the newest group may stay in flight */
        if (c < 3) asm volatile("cp.async.wait_group 1;" ::: "memory");
        else       asm volatile("cp.async.wait_group 0;" ::: "memory");
        __syncthreads();

        const uint32_t Ab = smb + GB_A_OFF + (uint32_t)(c & 1) * CHUNK_BYTES;
        const uint32_t Bh = smb + (uint32_t)(c & 1) * CHUNK_BYTES;
        const uint32_t Bl = smb + (uint32_t)(2 + (c & 1)) * CHUNK_BYTES;
        const bool do_bl = (c < 2);   /* Ah chunks hit Bh and Bl; Al only Bh */

#pragma unroll
        for (int k16 = 0; k16 < 4; k16++) {
            uint32_t afr[4][4];
#pragma unroll
            for (int mi = 0; mi < 4; mi++) {
                int row = m_w + mi * 16 + a_row;
                int ku = (k16 * 2 + a_ksel) ^ (row & 7);
                ldmx4(afr[mi][0], afr[mi][1], afr[mi][2], afr[mi][3],
                      Ab + (uint32_t)((row * 8 + ku) * 16));
            }
            /* Bh */
            {
                uint32_t bfr[4][2];
#pragma unroll
                for (int np = 0; np < 2; np++) {
                    int row = n_w + np * 16 + b_row;
                    int ku = (k16 * 2 + b_ksel) ^ (row & 7);
                    uint32_t r0, r1, r2, r3;
                    ldmx4(r0, r1, r2, r3, Bh + (uint32_t)((row * 8 + ku) * 16));
                    bfr[np * 2 + 0][0] = r0; bfr[np * 2 + 0][1] = r1;
                    bfr[np * 2 + 1][0] = r2; bfr[np * 2 + 1][1] = r3;
                }
#pragma unroll
                for (int mi = 0; mi < 4; mi++)
#pragma unroll
                    for (int ni = 0; ni < 4; ni++)
                        mma16816(acc[mi][ni], afr[mi], bfr[ni]);
            }
            /* Bl (Ah chunks only) — reuses the A fragments already loaded */
            if (do_bl) {
                uint32_t bfr[4][2];
#pragma unroll
                for (int np = 0; np < 2; np++) {
                    int row = n_w + np * 16 + b_row;
                    int ku = (k16 * 2 + b_ksel) ^ (row & 7);
                    uint32_t r0, r1, r2, r3;
                    ldmx4(r0, r1, r2, r3, Bl + (uint32_t)((row * 8 + ku) * 16));
                    bfr[np * 2 + 0][0] = r0; bfr[np * 2 + 0][1] = r1;
                    bfr[np * 2 + 1][0] = r2; bfr[np * 2 + 1][1] = r3;
                }
#pragma unroll
                for (int mi = 0; mi < 4; mi++)
#pragma unroll
                    for (int ni = 0; ni < 4; ni++)
                        mma16816(acc[mi][ni], afr[mi], bfr[ni]);
            }
        }
        __syncthreads();
        /* RACE FIX: only now is buffer (c&1) fully consumed — safe to
           refill it with chunk c+2. */
        if (c + 2 < 4) load_a(c + 2);
    }

    float2 bias[4];
#pragma unroll
    for (int ni = 0; ni < 4; ni++) {
        int col = n0 + n_w + ni * 8 + (lane & 3) * 2;
        bias[ni] = *reinterpret_cast<const float2*>(&b2[col]);
    }
#pragma unroll
    for (int mi = 0; mi < 4; mi++) {
        size_t r0 = m0 + m_w + mi * 16 + (lane >> 2);
#pragma unroll
        for (int ni = 0; ni < 4; ni++) {
            int col = n0 + n_w + ni * 8 + (lane & 3) * 2;
            float2 v0 = make_float2(acc[mi][ni][0] + bias[ni].x,
                                    acc[mi][ni][1] + bias[ni].y);
            float2 v1 = make_float2(acc[mi][ni][2] + bias[ni].x,
                                    acc[mi][ni][3] + bias[ni].y);
            *reinterpret_cast<float2*>(&g_trans[r0 * TRANS_N + col]) = v0;
            *reinterpret_cast<float2*>(&g_trans[(r0 + 8) * TRANS_N + col]) = v1;
        }
    }
}

/* ------------------------------------------------------------------ */
/* Kernel C: bulk-sync scan, T global->register, loop UNROLLED x4:     */
/* prefetch distance 4 (Tr0..Tr3, statically indexed — no spill).      */
/* R15 measured the distance-2 equilibrium T_step = L/2 = 561 ns;      */
/* distance 4 targets L/4.                                             */
/* ------------------------------------------------------------------ */
#define SC_RING 16

__global__ __launch_bounds__(192, 1) void scan_kernel(
    const float* __restrict__ init_hidden, float* __restrict__ out)
{
    __shared__ __align__(16) float u_ring[SC_RING][DS];
    __shared__ float inv_ring[SC_RING];
    __shared__ __align__(16) float p_s[8][DS];   /* [ib][j] partials */
    __shared__ float wsum[2];

    const int tid = threadIdx.x;
    const int b = blockIdx.x;
    const int lane = tid & 31;
    const int wid = tid >> 5;
    const float* __restrict__ trans = g_trans + (size_t)b * SEQ * TRANS_N;

    /* ---- init: normalized initial hidden into u_ring[15] ---- */
    float v0 = 0.f;
    if (tid < 64) {
        v0 = init_hidden[tid];
        float s = v0 * v0;
        s += __shfl_xor_sync(0xffffffffu, s, 16);
        s += __shfl_xor_sync(0xffffffffu, s, 8);
        s += __shfl_xor_sync(0xffffffffu, s, 4);
        s += __shfl_xor_sync(0xffffffffu, s, 2);
        s += __shfl_xor_sync(0xffffffffu, s, 1);
        if (lane == 0) wsum[tid >> 5] = s;
    }
    __syncthreads();
    if (tid < 64) {
        float inv = 1.f / fmaxf(sqrtf(wsum[0] + wsum[1]), 1e-12f);
        u_ring[SC_RING - 1][tid] = v0 * inv;
    }
    __syncthreads();

    const int jg = tid & 15;          /* column group (4 cols) */
    const int ib = tid >> 4;          /* row block (8 rows)    */
    const float* __restrict__ Tbase = trans + (size_t)(ib * 8) * 64 + jg * 4;

    float4 Tr0[8], Tr1[8], Tr2[8], Tr3[8];   /* static — stays in regs */
    if (wid < 4) {
#pragma unroll
        for (int k = 0; k < 8; k++) {
            Tr0[k] = *reinterpret_cast<const float4*>(Tbase + k * 64);
            Tr1[k] = *reinterpret_cast<const float4*>(Tbase + TRANS_N + k * 64);
            Tr2[k] = *reinterpret_cast<const float4*>(Tbase + 2 * TRANS_N + k * 64);
            Tr3[k] = *reinterpret_cast<const float4*>(Tbase + 3 * TRANS_N + k * 64);
        }
    }

#define SCAN_MATVEC(t, TBUF)                                               \
    do {                                                                   \
        const float4* up = reinterpret_cast<const float4*>(                \
            &u_ring[((t) + SC_RING - 1) & (SC_RING - 1)][ib * 8]);         \
        float4 ua = up[0];                                                 \
        float4 ub = up[1];                                                 \
        float4 acc;                                                        \
        acc.x = ua.x * TBUF[0].x; acc.y = ua.x * TBUF[0].y;                \
        acc.z = ua.x * TBUF[0].z; acc.w = ua.x * TBUF[0].w;                \
        acc.x = fmaf(ua.y, TBUF[1].x, acc.x);                              \
        acc.y = fmaf(ua.y, TBUF[1].y, acc.y);                              \
        acc.z = fmaf(ua.y, TBUF[1].z, acc.z);                              \
        acc.w = fmaf(ua.y, TBUF[1].w, acc.w);                              \
        acc.x = fmaf(ua.z, TBUF[2].x, acc.x);                              \
        acc.y = fmaf(ua.z, TBUF[2].y, acc.y);                              \
        acc.z = fmaf(ua.z, TBUF[2].z, acc.z);                              \
        acc.w = fmaf(ua.z, TBUF[2].w, acc.w);                              \
        acc.x = fmaf(ua.w, TBUF[3].x, acc.x);                              \
        acc.y = fmaf(ua.w, TBUF[3].y, acc.y);                              \
        acc.z = fmaf(ua.w, TBUF[3].z, acc.z);                              \
        acc.w = fmaf(ua.w, TBUF[3].w, acc.w);                              \
        acc.x = fmaf(ub.x, TBUF[4].x, acc.x);                              \
        acc.y = fmaf(ub.x, TBUF[4].y, acc.y);                              \
        acc.z = fmaf(ub.x, TBUF[4].z, acc.z);                              \
        acc.w = fmaf(ub.x, TBUF[4].w, acc.w);                              \
        acc.x = fmaf(ub.y, TBUF[5].x, acc.x);                              \
        acc.y = fmaf(ub.y, TBUF[5].y, acc.y);                              \
        acc.z = fmaf(ub.y, TBUF[5].z, acc.z);                              \
        acc.w = fmaf(ub.y, TBUF[5].w, acc.w);                              \
        acc.x = fmaf(ub.z, TBUF[6].x, acc.x);                              \
        acc.y = fmaf(ub.z, TBUF[6].y, acc.y);                              \
        acc.z = fmaf(ub.z, TBUF[6].z, acc.z);                              \
        acc.w = fmaf(ub.z, TBUF[6].w, acc.w);                              \
        acc.x = fmaf(ub.w, TBUF[7].x, acc.x);                              \
        acc.y = fmaf(ub.w, TBUF[7].y, acc.y);                              \
        acc.z = fmaf(ub.w, TBUF[7].z, acc.z);                              \
        acc.w = fmaf(ub.w, TBUF[7].w, acc.w);                              \
        *reinterpret_cast<float4*>(&p_s[ib][jg * 4]) = acc;                \
        if ((t) + 4 < SEQ) {                                               \
            const float* src = Tbase + (size_t)((t) + 4) * TRANS_N;        \
            _Pragma("unroll")                                              \
            for (int k = 0; k < 8; k++)                                    \
                TBUF[k] = *reinterpret_cast<const float4*>(src + k * 64);  \
        }                                                                  \
    } while (0)

#define SCAN_NORM(tp)                                                      \
    do {                                                                   \
        if ((tp) >= 0 && ((tp) & 1) == (wid - 4)) {                        \
            float2 u2 = *reinterpret_cast<const float2*>(                  \
                &u_ring[(tp) & (SC_RING - 1)][lane * 2]);                  \
            float ss = fmaf(u2.x, u2.x, u2.y * u2.y);                      \
            ss += __shfl_xor_sync(0xffffffffu, ss, 16);                    \
            ss += __shfl_xor_sync(0xffffffffu, ss, 8);                     \
            ss += __shfl_xor_sync(0xffffffffu, ss, 4);                     \
            ss += __shfl_xor_sync(0xffffffffu, ss, 2);                     \
            ss += __shfl_xor_sync(0xffffffffu, ss, 1);                     \
            float inv = 1.f / fmaxf(sqrtf(ss), 1e-12f);                    \
            *reinterpret_cast<float2*>(                                    \
                &out[((size_t)b * SEQ + (tp)) * DS + lane * 2]) =          \
                make_float2(u2.x * inv, u2.y * inv);                       \
            if (lane == 0) inv_ring[(tp) & (SC_RING - 1)] = inv;           \
        }                                                                  \
    } while (0)

#define SCAN_PHASEB(t)                                                     \
    do {                                                                   \
        if (tid < 64) {                                                    \
            float z = ((p_s[0][tid] + p_s[1][tid]) +                       \
                       (p_s[2][tid] + p_s[3][tid])) +                      \
                      ((p_s[4][tid] + p_s[5][tid]) +                       \
                       (p_s[6][tid] + p_s[7][tid]));                       \
            float u = fmaxf(z, 0.f);                                       \
            if ((t) >= 4) {                                                \
                unsigned ibq = __float_as_uint(                            \
                    inv_ring[((t) - 4) & (SC_RING - 1)]);                  \
                int e = (int)((ibq >> 23) & 0xFFu) - 127;                  \
                e = max(-96, min(96, e));                                  \
                float s = __uint_as_float(                                 \
                    (unsigned)(127 + (e >> 2)) << 23);                     \
                u *= s;                                                    \
            }                                                              \
            u_ring[(t) & (SC_RING - 1)][tid] = u;                          \
        }                                                                  \
    } while (0)

#define SCAN_STEP(t, TBUF)                                                 \
    do {                                                                   \
        if (wid < 4) SCAN_MATVEC(t, TBUF);                                 \
        else         SCAN_NORM((t) - 1);                                   \
        __syncthreads();                                                   \
        SCAN_PHASEB(t);                                                    \
        __syncthreads();                                                   \
    } while (0)

    for (int tt = 0; tt < SEQ; tt += 4) {
        SCAN_STEP(tt + 0, Tr0);
        SCAN_STEP(tt + 1, Tr1);
        SCAN_STEP(tt + 2, Tr2);
        SCAN_STEP(tt + 3, Tr3);
    }
    /* epilogue: norm+store for the final step */
    if (wid >= 4) SCAN_NORM(SEQ - 1);

#undef SCAN_MATVEC
#undef SCAN_NORM
#undef SCAN_PHASEB
#undef SCAN_STEP
}

/* ------------------------------------------------------------------ */
extern "C" void kernel_launch(void* const* d_in, const int* in_sizes, int n_in,
                              void* d_out, int out_size)
{
    const float* actions = (const float*)d_in[0];
    const float* w0 = (const float*)d_in[1];
    const float* b0 = (const float*)d_in[2];
    const float* w1 = (const float*)d_in[3];
    const float* b1 = (const float*)d_in[4];
    const float* w2 = (const float*)d_in[5];
    const float* b2 = (const float*)d_in[6];
    const float* ih = (const float*)d_in[7];
    float* out = (float*)d_out;

    mlp01_kernel<<<NTOK / 64, 256>>>(actions, w0, b0, w1, b1);
    convw2_kernel<<<dim3(TRANS_N / 32, HID / 32), dim3(32, 8)>>>(w2);

    cudaFuncSetAttribute(gemm_mma_kernel,
                         cudaFuncAttributeMaxDynamicSharedMemorySize, GB_DSMEM);
    gemm_mma_kernel<<<dim3(TRANS_N / 128, NTOK / 128), 256, GB_DSMEM>>>(b2);

    scan_kernel<<<BATCH, 192>>>(ih, out);
}